// round 14
// baseline (speedup 1.0000x reference)
#include <cuda_runtime.h>
#include <math.h>
#include <stdint.h>

#define Dm    1024
#define HEADS 16
#define HDIM  64
#define MLPD  4096
#define BATCH 2
#define SEQ   2048
#define ROWS  (BATCH*SEQ)   // 4096

// ---------------- scratch (no allocation allowed) ----------------
__device__ float g_h  [(size_t)ROWS*Dm];
__device__ float g_qkv[(size_t)ROWS*3*Dm];
__device__ float g_o  [(size_t)ROWS*Dm];
__device__ float g_x1 [(size_t)ROWS*Dm];
__device__ float g_m  [(size_t)ROWS*Dm];
__device__ float g_ma [(size_t)ROWS*MLPD];
__device__ float g_wt [(size_t)4*1024*1024];   // transposed weight staging [N][K-permuted]

__device__ float* const g_ptrs[7] = { g_h, g_qkv, g_o, g_x1, g_m, g_ma, g_wt };

__device__ __forceinline__ const float* resolve_c(int id, const float* ext) {
    return id < 0 ? ext : (const float*)g_ptrs[id];
}
__device__ __forceinline__ float* resolve_m(int id, float* ext) {
    return id < 0 ? ext : g_ptrs[id];
}

__device__ __forceinline__ uint32_t to_tf32(float f) {
    uint32_t r;
    asm("cvt.rna.tf32.f32 %0, %1;" : "=r"(r) : "f"(f));
    return r;
}

__device__ __forceinline__ void mma_tf32(float* d, const uint32_t* a, const uint32_t* b) {
    asm volatile(
        "mma.sync.aligned.m16n8k8.row.col.f32.tf32.tf32.f32 "
        "{%0,%1,%2,%3}, {%4,%5,%6,%7}, {%8,%9}, {%0,%1,%2,%3};"
        : "+f"(d[0]), "+f"(d[1]), "+f"(d[2]), "+f"(d[3])
        : "r"(a[0]), "r"(a[1]), "r"(a[2]), "r"(a[3]), "r"(b[0]), "r"(b[1]));
}

// ---------------- LayerNorm ----------------
__global__ void ln_kernel(int in_id, const float* __restrict__ x_ext,
                          const float* __restrict__ g, const float* __restrict__ b,
                          int out_id) {
    const float* x = resolve_c(in_id, x_ext);
    float* out = g_ptrs[out_id];
    int row = blockIdx.x;
    int tid = threadIdx.x;
    const float4* xr = (const float4*)(x + (size_t)row * Dm);
    float4 v = xr[tid];
    float s  = v.x + v.y + v.z + v.w;
    float ss = v.x*v.x + v.y*v.y + v.z*v.z + v.w*v.w;
    #pragma unroll
    for (int o = 16; o > 0; o >>= 1) {
        s  += __shfl_xor_sync(0xffffffffu, s,  o);
        ss += __shfl_xor_sync(0xffffffffu, ss, o);
    }
    __shared__ float sh_s[8], sh_ss[8];
    int w = tid >> 5, lane = tid & 31;
    if (lane == 0) { sh_s[w] = s; sh_ss[w] = ss; }
    __syncthreads();
    s = 0.f; ss = 0.f;
    #pragma unroll
    for (int i = 0; i < 8; i++) { s += sh_s[i]; ss += sh_ss[i]; }
    float mu  = s * (1.0f / Dm);
    float var = ss * (1.0f / Dm) - mu * mu;
    float r   = rsqrtf(var + 1e-5f);
    float4 gg = ((const float4*)g)[tid];
    float4 bb = ((const float4*)b)[tid];
    float4 o4;
    o4.x = (v.x - mu) * r * gg.x + bb.x;
    o4.y = (v.y - mu) * r * gg.y + bb.y;
    o4.z = (v.z - mu) * r * gg.z + bb.z;
    o4.w = (v.w - mu) * r * gg.w + bb.w;
    ((float4*)(out + (size_t)row * Dm))[tid] = o4;
}

// ---------------- weight transpose: W[K][N] -> g_wt[N][K-permuted] ----------------
__global__ void transpose_w(const float* __restrict__ W, int K, int N) {
    __shared__ float t[32][33];
    int bx = blockIdx.x * 32;   // n
    int by = blockIdx.y * 32;   // k
    int x = threadIdx.x, y = threadIdx.y;   // 32 x 8
    #pragma unroll
    for (int j = 0; j < 4; j++)
        t[y + 8*j][x] = W[(size_t)(by + y + 8*j) * N + bx + x];
    __syncthreads();
    int xp = (x & 24) | (2 * (x & 3)) | ((x >> 2) & 1);
    #pragma unroll
    for (int j = 0; j < 4; j++)
        g_wt[(size_t)(bx + y + 8*j) * K + by + xp] = t[x][y + 8*j];
}

// ---------------- GELU (exact) ----------------
__device__ __forceinline__ float gelu_f(float x) {
    return 0.5f * x * (1.0f + erff(x * 0.70710678118654752f));
}

// ---------------- tf32 mma.sync GEMM: double-buffered + register prefetch ----------------
#define PAD 40
#define GEMM_SMEM_BYTES (4 * 128 * PAD * 4)   // As0,As1,Bs0,Bs1 = 81920

template<int EPI>
__global__ __launch_bounds__(256)
void gemm_mma(int a_id, const float* __restrict__ bias,
              int res_id, const float* __restrict__ res_ext,
              int c_id, float* __restrict__ c_ext,
              int M, int N, int K) {
    const float* A  = (const float*)g_ptrs[a_id];
    const float* Bw = g_wt;
    const float* res = (EPI == 1) ? resolve_c(res_id, res_ext) : nullptr;
    float* C = resolve_m(c_id, c_ext);

    extern __shared__ __align__(16) uint32_t dsm[];
    uint32_t* AsB[2] = { dsm,               dsm + 128 * PAD     };
    uint32_t* BsB[2] = { dsm + 2*128*PAD,   dsm + 3*128*PAD     };

    const int tid  = threadIdx.x;
    const int wid  = tid >> 5, lane = tid & 31;
    const int row0 = blockIdx.y * 128;
    const int col0 = blockIdx.x * 128;
    const int mw   = (wid & 1) * 64;
    const int nw   = (wid >> 1) * 32;
    const int lr   = tid >> 1;
    const int lc   = (tid & 1) * 16;

    float acc[4][4][4];
    #pragma unroll
    for (int i = 0; i < 4; i++)
        #pragma unroll
        for (int j = 0; j < 4; j++)
            #pragma unroll
            for (int e = 0; e < 4; e++) acc[i][j][e] = 0.f;

    const int r4 = lane >> 2, c4 = lane & 3;
    const int T  = K >> 5;

    float4 pre_a[4], pre_b[4];

    // gmem tile -> registers
    auto load_tile = [&](int t) {
        const float4* pa = (const float4*)(A  + (size_t)(row0 + lr) * K + t * 32 + lc);
        const float4* pb = (const float4*)(Bw + (size_t)(col0 + lr) * K + t * 32 + lc);
        #pragma unroll
        for (int j = 0; j < 4; j++) { pre_a[j] = pa[j]; pre_b[j] = pb[j]; }
    };
    // registers -> smem buffer (tf32 convert; A pair-permuted, B pre-permuted)
    auto store_tile = [&](uint32_t* As, uint32_t* Bs) {
        uint32_t* dst = &As[lr * PAD + lc];
        *(uint2*)&dst[0]  = make_uint2(to_tf32(pre_a[0].x), to_tf32(pre_a[1].x));
        *(uint2*)&dst[2]  = make_uint2(to_tf32(pre_a[0].y), to_tf32(pre_a[1].y));
        *(uint2*)&dst[4]  = make_uint2(to_tf32(pre_a[0].z), to_tf32(pre_a[1].z));
        *(uint2*)&dst[6]  = make_uint2(to_tf32(pre_a[0].w), to_tf32(pre_a[1].w));
        *(uint2*)&dst[8]  = make_uint2(to_tf32(pre_a[2].x), to_tf32(pre_a[3].x));
        *(uint2*)&dst[10] = make_uint2(to_tf32(pre_a[2].y), to_tf32(pre_a[3].y));
        *(uint2*)&dst[12] = make_uint2(to_tf32(pre_a[2].z), to_tf32(pre_a[3].z));
        *(uint2*)&dst[14] = make_uint2(to_tf32(pre_a[2].w), to_tf32(pre_a[3].w));
        #pragma unroll
        for (int j = 0; j < 4; j++) {
            uint4 ub = { to_tf32(pre_b[j].x), to_tf32(pre_b[j].y),
                         to_tf32(pre_b[j].z), to_tf32(pre_b[j].w) };
            *(uint4*)&Bs[lr * PAD + lc + 4*j] = ub;
        }
    };

    load_tile(0);
    store_tile(AsB[0], BsB[0]);
    __syncthreads();

    for (int t = 0; t < T; t++) {
        const int cur = t & 1;
        if (t + 1 < T) load_tile(t + 1);   // LDGs in flight during mma phase

        const uint32_t* As = AsB[cur];
        const uint32_t* Bs = BsB[cur];
        #pragma unroll
        for (int ks = 0; ks < 4; ks++) {
            const int kb = ks * 8 + 2 * c4;
            uint32_t afr[4][4];
            #pragma unroll
            for (int mt = 0; mt < 4; mt++) {
                int m = mw + mt * 16;
                uint2 a01 = *(const uint2*)&As[(m + r4)     * PAD + kb];
                uint2 a23 = *(const uint2*)&As[(m + r4 + 8) * PAD + kb];
                afr[mt][0] = a01.x; afr[mt][1] = a23.x;
                afr[mt][2] = a01.y; afr[mt][3] = a23.y;
            }
            uint32_t bfr[4][2];
            #pragma unroll
            for (int nt = 0; nt < 4; nt++) {
                uint2 bq = *(const uint2*)&Bs[(nw + nt * 8 + r4) * PAD + kb];
                bfr[nt][0] = bq.x; bfr[nt][1] = bq.y;
            }
            #pragma unroll
            for (int mt = 0; mt < 4; mt++)
                #pragma unroll
                for (int nt = 0; nt < 4; nt++)
                    mma_tf32(acc[mt][nt], afr[mt], bfr[nt]);
        }

        if (t + 1 < T) store_tile(AsB[cur ^ 1], BsB[cur ^ 1]);
        __syncthreads();
    }

    #pragma unroll
    for (int mt = 0; mt < 4; mt++) {
        #pragma unroll
        for (int nt = 0; nt < 4; nt++) {
            int gm = row0 + mw + mt * 16 + r4;
            int gn = col0 + nw + nt * 8 + 2 * c4;
            float2 bi = *(const float2*)(bias + gn);
            #pragma unroll
            for (int half = 0; half < 2; half++) {
                int rr = gm + half * 8;
                float2 v;
                v.x = acc[mt][nt][half*2 + 0] + bi.x;
                v.y = acc[mt][nt][half*2 + 1] + bi.y;
                if (EPI == 1) {
                    float2 r2 = *(const float2*)(res + (size_t)rr * N + gn);
                    v.x += r2.x; v.y += r2.y;
                }
                if (EPI == 2) { v.x = gelu_f(v.x); v.y = gelu_f(v.y); }
                *(float2*)(C + (size_t)rr * N + gn) = v;
            }
        }
    }
}

// ---------------- tensor-core flash attention v2 (unchanged from R13) ----------------
#define AQW 72
#define ATT_SMEM_BYTES ((128*AQW + 64*AQW + 64*AQW) * 4)   // 73728

__global__ __launch_bounds__(128)
void attn_mma() {
    extern __shared__ __align__(16) uint32_t dsm[];
    uint32_t* Qs = dsm;                 // 128 x AQW
    uint32_t* Ks = dsm + 128 * AQW;     // 64 x AQW
    uint32_t* Vt = Ks  + 64 * AQW;      // 64 x AQW

    const int tid  = threadIdx.x;
    const int wid  = tid >> 5, lane = tid & 31;
    const int r4   = lane >> 2, c4 = lane & 3;
    const int bh   = blockIdx.y;
    const int b    = bh / HEADS, h = bh % HEADS;
    const int q0   = blockIdx.x * 128;
    const float* base = g_qkv + (size_t)b * SEQ * (3 * Dm);
    const int ldq  = 3 * Dm;

    const int srow = tid >> 1, shalf = tid & 1;
    const int prow = (srow & ~7) | (2 * (srow & 3)) | ((srow >> 2) & 1);

    {
        const float4* src = (const float4*)(base + (size_t)(q0 + tid) * ldq + h * HDIM);
        uint32_t* dst = &Qs[tid * AQW];
        #pragma unroll
        for (int g = 0; g < 8; g++) {
            float4 v0 = src[2*g], v1 = src[2*g + 1];
            uint32_t* d8 = dst + g * 8;
            *(uint2*)&d8[0] = make_uint2(to_tf32(v0.x * 0.125f), to_tf32(v1.x * 0.125f));
            *(uint2*)&d8[2] = make_uint2(to_tf32(v0.y * 0.125f), to_tf32(v1.y * 0.125f));
            *(uint2*)&d8[4] = make_uint2(to_tf32(v0.z * 0.125f), to_tf32(v1.z * 0.125f));
            *(uint2*)&d8[6] = make_uint2(to_tf32(v0.w * 0.125f), to_tf32(v1.w * 0.125f));
        }
    }

    float accO[2][8][4];
    #pragma unroll
    for (int mt = 0; mt < 2; mt++)
        #pragma unroll
        for (int nt = 0; nt < 8; nt++)
            #pragma unroll
            for (int e = 0; e < 4; e++) accO[mt][nt][e] = 0.f;
    float m_lo[2] = {-1e30f, -1e30f}, m_hi[2] = {-1e30f, -1e30f};
    float l_lo[2] = {0.f, 0.f},       l_hi[2] = {0.f, 0.f};

    const int  srcA = (r4 << 2) | (c4 >> 1);
    const int  srcB = srcA + 2;
    const bool odd  = (c4 & 1);
    const int  mrow0 = wid * 32;

    for (int kt = 0; kt < SEQ; kt += 64) {
        __syncthreads();
        {
            const float* krow = base + (size_t)(kt + srow) * ldq + Dm + h * HDIM + shalf * 32;
            const float4* ksrc = (const float4*)krow;
            uint32_t* kdst = &Ks[srow * AQW + shalf * 32];
            #pragma unroll
            for (int g = 0; g < 4; g++) {
                float4 v0 = ksrc[2*g], v1 = ksrc[2*g + 1];
                uint32_t* d8 = kdst + g * 8;
                *(uint2*)&d8[0] = make_uint2(to_tf32(v0.x), to_tf32(v1.x));
                *(uint2*)&d8[2] = make_uint2(to_tf32(v0.y), to_tf32(v1.y));
                *(uint2*)&d8[4] = make_uint2(to_tf32(v0.z), to_tf32(v1.z));
                *(uint2*)&d8[6] = make_uint2(to_tf32(v0.w), to_tf32(v1.w));
            }
            const float4* vsrc = (const float4*)(krow + Dm);
            #pragma unroll
            for (int j = 0; j < 8; j++) {
                float4 v = vsrc[j];
                int d = shalf * 32 + 4 * j;
                Vt[(d+0) * AQW + prow] = to_tf32(v.x);
                Vt[(d+1) * AQW + prow] = to_tf32(v.y);
                Vt[(d+2) * AQW + prow] = to_tf32(v.z);
                Vt[(d+3) * AQW + prow] = to_tf32(v.w);
            }
        }
        __syncthreads();

        float accS[2][8][4];
        #pragma unroll
        for (int mt = 0; mt < 2; mt++)
            #pragma unroll
            for (int nt = 0; nt < 8; nt++)
                #pragma unroll
                for (int e = 0; e < 4; e++) accS[mt][nt][e] = 0.f;
        #pragma unroll
        for (int ks = 0; ks < 8; ks++) {
            const int kb = ks * 8 + 2 * c4;
            uint32_t afr[2][4];
            #pragma unroll
            for (int mt = 0; mt < 2; mt++) {
                int m = mrow0 + mt * 16;
                uint2 a01 = *(const uint2*)&Qs[(m + r4)     * AQW + kb];
                uint2 a23 = *(const uint2*)&Qs[(m + r4 + 8) * AQW + kb];
                afr[mt][0] = a01.x; afr[mt][1] = a23.x;
                afr[mt][2] = a01.y; afr[mt][3] = a23.y;
            }
            #pragma unroll
            for (int nt = 0; nt < 8; nt++) {
                uint2 bq = *(const uint2*)&Ks[(nt*8 + r4) * AQW + kb];
                uint32_t bfr[2] = { bq.x, bq.y };
                mma_tf32(accS[0][nt], afr[0], bfr);
                mma_tf32(accS[1][nt], afr[1], bfr);
            }
        }

        #pragma unroll
        for (int mt = 0; mt < 2; mt++) {
            float rmax_lo = -1e30f, rmax_hi = -1e30f;
            #pragma unroll
            for (int nt = 0; nt < 8; nt++) {
                rmax_lo = fmaxf(rmax_lo, fmaxf(accS[mt][nt][0], accS[mt][nt][1]));
                rmax_hi = fmaxf(rmax_hi, fmaxf(accS[mt][nt][2], accS[mt][nt][3]));
            }
            rmax_lo = fmaxf(rmax_lo, __shfl_xor_sync(0xffffffffu, rmax_lo, 1));
            rmax_lo = fmaxf(rmax_lo, __shfl_xor_sync(0xffffffffu, rmax_lo, 2));
            rmax_hi = fmaxf(rmax_hi, __shfl_xor_sync(0xffffffffu, rmax_hi, 1));
            rmax_hi = fmaxf(rmax_hi, __shfl_xor_sync(0xffffffffu, rmax_hi, 2));

            float mn_lo = fmaxf(m_lo[mt], rmax_lo);
            float mn_hi = fmaxf(m_hi[mt], rmax_hi);
            float corr_lo = __expf(m_lo[mt] - mn_lo);
            float corr_hi = __expf(m_hi[mt] - mn_hi);
            m_lo[mt] = mn_lo; m_hi[mt] = mn_hi;

            float rs_lo = 0.f, rs_hi = 0.f;
            #pragma unroll
            for (int nt = 0; nt < 8; nt++) {
                float p0 = __expf(accS[mt][nt][0] - mn_lo);
                float p1 = __expf(accS[mt][nt][1] - mn_lo);
                float p2 = __expf(accS[mt][nt][2] - mn_hi);
                float p3 = __expf(accS[mt][nt][3] - mn_hi);
                rs_lo += p0 + p1; rs_hi += p2 + p3;
                accS[mt][nt][0] = p0; accS[mt][nt][1] = p1;
                accS[mt][nt][2] = p2; accS[mt][nt][3] = p3;
            }
            rs_lo += __shfl_xor_sync(0xffffffffu, rs_lo, 1);
            rs_lo += __shfl_xor_sync(0xffffffffu, rs_lo, 2);
            rs_hi += __shfl_xor_sync(0xffffffffu, rs_hi, 1);
            rs_hi += __shfl_xor_sync(0xffffffffu, rs_hi, 2);
            l_lo[mt] = l_lo[mt] * corr_lo + rs_lo;
            l_hi[mt] = l_hi[mt] * corr_hi + rs_hi;

            #pragma unroll
            for (int nt = 0; nt < 8; nt++) {
                accO[mt][nt][0] *= corr_lo; accO[mt][nt][1] *= corr_lo;
                accO[mt][nt][2] *= corr_hi; accO[mt][nt][3] *= corr_hi;
            }
        }

        #pragma unroll
        for (int ks = 0; ks < 8; ks++) {
            uint32_t a_u[2][4];
            #pragma unroll
            for (int mt = 0; mt < 2; mt++) {
                float t0, t1, af;
                t0 = __shfl_sync(0xffffffffu, accS[mt][ks][0], srcA);
                t1 = __shfl_sync(0xffffffffu, accS[mt][ks][1], srcA);
                af = odd ? t1 : t0; a_u[mt][0] = to_tf32(af);
                t0 = __shfl_sync(0xffffffffu, accS[mt][ks][2], srcA);
                t1 = __shfl_sync(0xffffffffu, accS[mt][ks][3], srcA);
                af = odd ? t1 : t0; a_u[mt][1] = to_tf32(af);
                t0 = __shfl_sync(0xffffffffu, accS[mt][ks][0], srcB);
                t1 = __shfl_sync(0xffffffffu, accS[mt][ks][1], srcB);
                af = odd ? t1 : t0; a_u[mt][2] = to_tf32(af);
                t0 = __shfl_sync(0xffffffffu, accS[mt][ks][2], srcB);
                t1 = __shfl_sync(0xffffffffu, accS[mt][ks][3], srcB);
                af = odd ? t1 : t0; a_u[mt][3] = to_tf32(af);
            }
            const int kb = ks * 8 + 2 * c4;
            #pragma unroll
            for (int nt = 0; nt < 8; nt++) {
                uint2 bq = *(const uint2*)&Vt[(nt*8 + r4) * AQW + kb];
                uint32_t bfr[2] = { bq.x, bq.y };
                mma_tf32(accO[0][nt], a_u[0], bfr);
                mma_tf32(accO[1][nt], a_u[1], bfr);
            }
        }
    }

    #pragma unroll
    for (int mt = 0; mt < 2; mt++) {
        float il_lo = 1.0f / l_lo[mt], il_hi = 1.0f / l_hi[mt];
        int row_lo = q0 + mrow0 + mt * 16 + r4;
        float* o_lo = g_o + (size_t)(b * SEQ + row_lo) * Dm + h * HDIM;
        float* o_hi = o_lo + 8 * Dm;
        #pragma unroll
        for (int nt = 0; nt < 8; nt++) {
            float2 v;
            v.x = accO[mt][nt][0] * il_lo; v.y = accO[mt][nt][1] * il_lo;
            *(float2*)(o_lo + nt * 8 + 2 * c4) = v;
            v.x = accO[mt][nt][2] * il_hi; v.y = accO[mt][nt][3] * il_hi;
            *(float2*)(o_hi + nt * 8 + 2 * c4) = v;
        }
    }
}

// ---------------- launch ----------------
// Buffer ids: 0=g_h 1=g_qkv 2=g_o 3=g_x1 4=g_m 5=g_ma 6=g_wt ; -1 = external
extern "C" void kernel_launch(void* const* d_in, const int* in_sizes, int n_in,
                              void* d_out, int out_size) {
    const float* x      = (const float*)d_in[0];
    const float* ln1_g  = (const float*)d_in[1];
    const float* ln1_b  = (const float*)d_in[2];
    const float* lnm_g  = (const float*)d_in[3];
    const float* lnm_b  = (const float*)d_in[4];
    const float* qkv_w  = (const float*)d_in[5];
    const float* qkv_b  = (const float*)d_in[6];
    const float* proj_w = (const float*)d_in[7];
    const float* proj_b = (const float*)d_in[8];
    const float* fc1_w  = (const float*)d_in[9];
    const float* fc1_b  = (const float*)d_in[10];
    const float* fc2_w  = (const float*)d_in[11];
    const float* fc2_b  = (const float*)d_in[12];
    float* out = (float*)d_out;

    // idempotent, non-stream API calls (execute immediately, not captured)
    cudaFuncSetAttribute(attn_mma, cudaFuncAttributeMaxDynamicSharedMemorySize,
                         ATT_SMEM_BYTES);
    cudaFuncSetAttribute(gemm_mma<0>, cudaFuncAttributeMaxDynamicSharedMemorySize,
                         GEMM_SMEM_BYTES);
    cudaFuncSetAttribute(gemm_mma<1>, cudaFuncAttributeMaxDynamicSharedMemorySize,
                         GEMM_SMEM_BYTES);
    cudaFuncSetAttribute(gemm_mma<2>, cudaFuncAttributeMaxDynamicSharedMemorySize,
                         GEMM_SMEM_BYTES);

    // 1. LN1: g_h = LN(x)
    ln_kernel<<<ROWS, 256>>>(-1, x, ln1_g, ln1_b, 0);
    // 2. QKV: g_qkv = g_h @ qkv_w + qkv_b
    transpose_w<<<dim3(3 * Dm / 32, Dm / 32), dim3(32, 8)>>>(qkv_w, Dm, 3 * Dm);
    gemm_mma<0><<<dim3(3 * Dm / 128, ROWS / 128), 256, GEMM_SMEM_BYTES>>>(
        0, qkv_b, -1, nullptr, 1, nullptr, ROWS, 3 * Dm, Dm);
    // 3. attention (tensor-core flash, Q-tile 128)
    attn_mma<<<dim3(SEQ / 128, BATCH * HEADS), 128, ATT_SMEM_BYTES>>>();
    // 4. g_x1 = x + g_o @ proj_w + proj_b
    transpose_w<<<dim3(Dm / 32, Dm / 32), dim3(32, 8)>>>(proj_w, Dm, Dm);
    gemm_mma<1><<<dim3(Dm / 128, ROWS / 128), 256, GEMM_SMEM_BYTES>>>(
        2, proj_b, -1, x, 3, nullptr, ROWS, Dm, Dm);
    // 5. LNm: g_m = LN(g_x1)
    ln_kernel<<<ROWS, 256>>>(3, nullptr, lnm_g, lnm_b, 4);
    // 6. g_ma = gelu(g_m @ fc1_w + fc1_b)
    transpose_w<<<dim3(MLPD / 32, Dm / 32), dim3(32, 8)>>>(fc1_w, Dm, MLPD);
    gemm_mma<2><<<dim3(MLPD / 128, ROWS / 128), 256, GEMM_SMEM_BYTES>>>(
        4, fc1_b, -1, nullptr, 5, nullptr, ROWS, MLPD, Dm);
    // 7. out = g_x1 + g_ma @ fc2_w + fc2_b
    transpose_w<<<dim3(Dm / 32, MLPD / 32), dim3(32, 8)>>>(fc2_w, MLPD, Dm);
    gemm_mma<1><<<dim3(Dm / 128, ROWS / 128), 256, GEMM_SMEM_BYTES>>>(
        5, fc2_b, 3, nullptr, -1, out, ROWS, Dm, MLPD);
}

// round 17
// speedup vs baseline: 1.4151x; 1.4151x over previous
#include <cuda_runtime.h>
#include <math.h>
#include <stdint.h>

#define Dm    1024
#define HEADS 16
#define HDIM  64
#define MLPD  4096
#define BATCH 2
#define SEQ   2048
#define ROWS  (BATCH*SEQ)   // 4096

// ---------------- scratch (no allocation allowed) ----------------
__device__ float g_h  [(size_t)ROWS*Dm];
__device__ float g_qkv[(size_t)ROWS*3*Dm];
__device__ float g_o  [(size_t)ROWS*Dm];
__device__ float g_x1 [(size_t)ROWS*Dm];
__device__ float g_m  [(size_t)ROWS*Dm];
__device__ float g_ma [(size_t)ROWS*MLPD];
__device__ float g_wt [(size_t)4*1024*1024];   // transposed weights [N][K-permuted], tf32-rounded

__device__ float* const g_ptrs[7] = { g_h, g_qkv, g_o, g_x1, g_m, g_ma, g_wt };

__device__ __forceinline__ const float* resolve_c(int id, const float* ext) {
    return id < 0 ? ext : (const float*)g_ptrs[id];
}
__device__ __forceinline__ float* resolve_m(int id, float* ext) {
    return id < 0 ? ext : g_ptrs[id];
}

__device__ __forceinline__ uint32_t to_tf32(float f) {
    uint32_t r;
    asm("cvt.rna.tf32.f32 %0, %1;" : "=r"(r) : "f"(f));
    return r;
}
__device__ __forceinline__ float tf32r(float f) {   // rna-rounded tf32 as float
    return __uint_as_float(to_tf32(f));
}

__device__ __forceinline__ void mma_tf32(float* d, const uint32_t* a, const uint32_t* b) {
    asm volatile(
        "mma.sync.aligned.m16n8k8.row.col.f32.tf32.tf32.f32 "
        "{%0,%1,%2,%3}, {%4,%5,%6,%7}, {%8,%9}, {%0,%1,%2,%3};"
        : "+f"(d[0]), "+f"(d[1]), "+f"(d[2]), "+f"(d[3])
        : "r"(a[0]), "r"(a[1]), "r"(a[2]), "r"(a[3]), "r"(b[0]), "r"(b[1]));
}

__device__ __forceinline__ void cp_async16(uint32_t* smem_dst, const void* gsrc) {
    uint32_t s = (uint32_t)__cvta_generic_to_shared(smem_dst);
    asm volatile("cp.async.cg.shared.global [%0], [%1], 16;" :: "r"(s), "l"(gsrc));
}
#define CP_COMMIT()  asm volatile("cp.async.commit_group;" ::: "memory")
#define CP_WAIT(n)   asm volatile("cp.async.wait_group %0;" :: "n"(n) : "memory")

// ---------------- LayerNorm (output tf32-rounded: feeds GEMM A only) ----------------
__global__ void ln_kernel(int in_id, const float* __restrict__ x_ext,
                          const float* __restrict__ g, const float* __restrict__ b,
                          int out_id) {
    const float* x = resolve_c(in_id, x_ext);
    float* out = g_ptrs[out_id];
    int row = blockIdx.x;
    int tid = threadIdx.x;
    const float4* xr = (const float4*)(x + (size_t)row * Dm);
    float4 v = xr[tid];
    float s  = v.x + v.y + v.z + v.w;
    float ss = v.x*v.x + v.y*v.y + v.z*v.z + v.w*v.w;
    #pragma unroll
    for (int o = 16; o > 0; o >>= 1) {
        s  += __shfl_xor_sync(0xffffffffu, s,  o);
        ss += __shfl_xor_sync(0xffffffffu, ss, o);
    }
    __shared__ float sh_s[8], sh_ss[8];
    int w = tid >> 5, lane = tid & 31;
    if (lane == 0) { sh_s[w] = s; sh_ss[w] = ss; }
    __syncthreads();
    s = 0.f; ss = 0.f;
    #pragma unroll
    for (int i = 0; i < 8; i++) { s += sh_s[i]; ss += sh_ss[i]; }
    float mu  = s * (1.0f / Dm);
    float var = ss * (1.0f / Dm) - mu * mu;
    float r   = rsqrtf(var + 1e-5f);
    float4 gg = ((const float4*)g)[tid];
    float4 bb = ((const float4*)b)[tid];
    float4 o4;
    o4.x = tf32r((v.x - mu) * r * gg.x + bb.x);
    o4.y = tf32r((v.y - mu) * r * gg.y + bb.y);
    o4.z = tf32r((v.z - mu) * r * gg.z + bb.z);
    o4.w = tf32r((v.w - mu) * r * gg.w + bb.w);
    ((float4*)(out + (size_t)row * Dm))[tid] = o4;
}

// ---------------- weight transpose: W[K][N] -> g_wt[N][K-permuted], tf32 bits ----------------
__global__ void transpose_w(const float* __restrict__ W, int K, int N) {
    __shared__ float t[32][33];
    int bx = blockIdx.x * 32;   // n
    int by = blockIdx.y * 32;   // k
    int x = threadIdx.x, y = threadIdx.y;   // 32 x 8
    #pragma unroll
    for (int j = 0; j < 4; j++)
        t[y + 8*j][x] = W[(size_t)(by + y + 8*j) * N + bx + x];
    __syncthreads();
    int xp = (x & 24) | (2 * (x & 3)) | ((x >> 2) & 1);
    #pragma unroll
    for (int j = 0; j < 4; j++)
        g_wt[(size_t)(bx + y + 8*j) * K + by + xp] = tf32r(t[x][y + 8*j]);
}

// ---------------- GELU (exact) ----------------
__device__ __forceinline__ float gelu_f(float x) {
    return 0.5f * x * (1.0f + erff(x * 0.70710678118654752f));
}

// ---------------- tf32 mma.sync GEMM: cp.async 2-stage pipeline ----------------
// A staged raw (producers pre-rounded) natural layout [128][AW]; frags via LDS.32.
// B staged raw (g_wt pre-rounded+permuted) layout [128][BW]; frags via LDS.64.
#define AW 36
#define BW 40
#define STAGE_W (128*AW + 128*BW)             // 9728 words
#define GEMM_SMEM_BYTES (2 * STAGE_W * 4)     // 77824 B

template<int EPI>
__global__ __launch_bounds__(256)
void gemm_mma(int a_id, const float* __restrict__ bias,
              int res_id, const float* __restrict__ res_ext,
              int c_id, float* __restrict__ c_ext,
              int M, int N, int K) {
    const float* A  = (const float*)g_ptrs[a_id];
    const float* Bw = g_wt;
    const float* res = (EPI == 1) ? resolve_c(res_id, res_ext) : nullptr;
    float* C = resolve_m(c_id, c_ext);

    extern __shared__ __align__(16) uint32_t dsm[];

    const int tid  = threadIdx.x;
    const int wid  = tid >> 5, lane = tid & 31;
    const int row0 = blockIdx.y * 128;
    const int col0 = blockIdx.x * 128;
    const int mw   = (wid & 1) * 64;
    const int nw   = (wid >> 1) * 32;
    const int lr   = tid >> 1;
    const int lc   = (tid & 1) * 16;

    float acc[4][4][4];
    #pragma unroll
    for (int i = 0; i < 4; i++)
        #pragma unroll
        for (int j = 0; j < 4; j++)
            #pragma unroll
            for (int e = 0; e < 4; e++) acc[i][j][e] = 0.f;

    const int r4 = lane >> 2, c4 = lane & 3;
    const int T  = K >> 5;

    auto stage = [&](int t, int s) {
        uint32_t* As = dsm + s * STAGE_W;
        uint32_t* Bs = As + 128 * AW;
        const float* pa = A  + (size_t)(row0 + lr) * K + t * 32 + lc;
        const float* pb = Bw + (size_t)(col0 + lr) * K + t * 32 + lc;
        #pragma unroll
        for (int j = 0; j < 4; j++) {
            cp_async16(&As[lr * AW + lc + 4*j], pa + 4*j);
            cp_async16(&Bs[lr * BW + lc + 4*j], pb + 4*j);
        }
    };

    stage(0, 0); CP_COMMIT();
    stage(1, 1); CP_COMMIT();

    for (int t = 0; t < T; t++) {
        if (t + 1 < T) { CP_WAIT(1); } else { CP_WAIT(0); }
        __syncthreads();

        const uint32_t* As = dsm + (t & 1) * STAGE_W;
        const uint32_t* Bs = As + 128 * AW;
        #pragma unroll
        for (int ks = 0; ks < 4; ks++) {
            const int ka  = ks * 8;             // natural order for A
            const int kbp = ks * 8 + 2 * c4;    // permuted for B
            uint32_t afr[4][4];
            #pragma unroll
            for (int mt = 0; mt < 4; mt++) {
                int m = mw + mt * 16;
                afr[mt][0] = As[(m + r4)     * AW + ka + c4];
                afr[mt][1] = As[(m + r4 + 8) * AW + ka + c4];
                afr[mt][2] = As[(m + r4)     * AW + ka + c4 + 4];
                afr[mt][3] = As[(m + r4 + 8) * AW + ka + c4 + 4];
            }
            uint32_t bfr[4][2];
            #pragma unroll
            for (int nt = 0; nt < 4; nt++) {
                uint2 bq = *(const uint2*)&Bs[(nw + nt * 8 + r4) * BW + kbp];
                bfr[nt][0] = bq.x; bfr[nt][1] = bq.y;
            }
            #pragma unroll
            for (int mt = 0; mt < 4; mt++)
                #pragma unroll
                for (int nt = 0; nt < 4; nt++)
                    mma_tf32(acc[mt][nt], afr[mt], bfr[nt]);
        }
        __syncthreads();
        if (t + 2 < T) { stage(t + 2, t & 1); }
        CP_COMMIT();
    }

    #pragma unroll
    for (int mt = 0; mt < 4; mt++) {
        #pragma unroll
        for (int nt = 0; nt < 4; nt++) {
            int gm = row0 + mw + mt * 16 + r4;
            int gn = col0 + nw + nt * 8 + 2 * c4;
            float2 bi = *(const float2*)(bias + gn);
            #pragma unroll
            for (int half = 0; half < 2; half++) {
                int rr = gm + half * 8;
                float2 v;
                v.x = acc[mt][nt][half*2 + 0] + bi.x;
                v.y = acc[mt][nt][half*2 + 1] + bi.y;
                if (EPI == 1) {
                    float2 r2 = *(const float2*)(res + (size_t)rr * N + gn);
                    v.x += r2.x; v.y += r2.y;
                }
                if (EPI == 2) { v.x = tf32r(gelu_f(v.x)); v.y = tf32r(gelu_f(v.y)); }
                *(float2*)(C + (size_t)rr * N + gn) = v;
            }
        }
    }
}

// ---------------- tensor-core flash attention v2 (R13, output tf32-rounded) ----------------
#define AQW 72
#define ATT_SMEM_BYTES ((128*AQW + 64*AQW + 64*AQW) * 4)   // 73728

__global__ __launch_bounds__(128)
void attn_mma() {
    extern __shared__ __align__(16) uint32_t dsm[];
    uint32_t* Qs = dsm;                 // 128 x AQW
    uint32_t* Ks = dsm + 128 * AQW;     // 64 x AQW
    uint32_t* Vt = Ks  + 64 * AQW;      // 64 x AQW

    const int tid  = threadIdx.x;
    const int wid  = tid >> 5, lane = tid & 31;
    const int r4   = lane >> 2, c4 = lane & 3;
    const int bh   = blockIdx.y;
    const int b    = bh / HEADS, h = bh % HEADS;
    const int q0   = blockIdx.x * 128;
    const float* base = g_qkv + (size_t)b * SEQ * (3 * Dm);
    const int ldq  = 3 * Dm;

    const int srow = tid >> 1, shalf = tid & 1;
    const int prow = (srow & ~7) | (2 * (srow & 3)) | ((srow >> 2) & 1);

    {
        const float4* src = (const float4*)(base + (size_t)(q0 + tid) * ldq + h * HDIM);
        uint32_t* dst = &Qs[tid * AQW];
        #pragma unroll
        for (int g = 0; g < 8; g++) {
            float4 v0 = src[2*g], v1 = src[2*g + 1];
            uint32_t* d8 = dst + g * 8;
            *(uint2*)&d8[0] = make_uint2(to_tf32(v0.x * 0.125f), to_tf32(v1.x * 0.125f));
            *(uint2*)&d8[2] = make_uint2(to_tf32(v0.y * 0.125f), to_tf32(v1.y * 0.125f));
            *(uint2*)&d8[4] = make_uint2(to_tf32(v0.z * 0.125f), to_tf32(v1.z * 0.125f));
            *(uint2*)&d8[6] = make_uint2(to_tf32(v0.w * 0.125f), to_tf32(v1.w * 0.125f));
        }
    }

    float accO[2][8][4];
    #pragma unroll
    for (int mt = 0; mt < 2; mt++)
        #pragma unroll
        for (int nt = 0; nt < 8; nt++)
            #pragma unroll
            for (int e = 0; e < 4; e++) accO[mt][nt][e] = 0.f;
    float m_lo[2] = {-1e30f, -1e30f}, m_hi[2] = {-1e30f, -1e30f};
    float l_lo[2] = {0.f, 0.f},       l_hi[2] = {0.f, 0.f};

    const int  srcA = (r4 << 2) | (c4 >> 1);
    const int  srcB = srcA + 2;
    const bool odd  = (c4 & 1);
    const int  mrow0 = wid * 32;

    for (int kt = 0; kt < SEQ; kt += 64) {
        __syncthreads();
        {
            const float* krow = base + (size_t)(kt + srow) * ldq + Dm + h * HDIM + shalf * 32;
            const float4* ksrc = (const float4*)krow;
            uint32_t* kdst = &Ks[srow * AQW + shalf * 32];
            #pragma unroll
            for (int g = 0; g < 4; g++) {
                float4 v0 = ksrc[2*g], v1 = ksrc[2*g + 1];
                uint32_t* d8 = kdst + g * 8;
                *(uint2*)&d8[0] = make_uint2(to_tf32(v0.x), to_tf32(v1.x));
                *(uint2*)&d8[2] = make_uint2(to_tf32(v0.y), to_tf32(v1.y));
                *(uint2*)&d8[4] = make_uint2(to_tf32(v0.z), to_tf32(v1.z));
                *(uint2*)&d8[6] = make_uint2(to_tf32(v0.w), to_tf32(v1.w));
            }
            const float4* vsrc = (const float4*)(krow + Dm);
            #pragma unroll
            for (int j = 0; j < 8; j++) {
                float4 v = vsrc[j];
                int d = shalf * 32 + 4 * j;
                Vt[(d+0) * AQW + prow] = to_tf32(v.x);
                Vt[(d+1) * AQW + prow] = to_tf32(v.y);
                Vt[(d+2) * AQW + prow] = to_tf32(v.z);
                Vt[(d+3) * AQW + prow] = to_tf32(v.w);
            }
        }
        __syncthreads();

        float accS[2][8][4];
        #pragma unroll
        for (int mt = 0; mt < 2; mt++)
            #pragma unroll
            for (int nt = 0; nt < 8; nt++)
                #pragma unroll
                for (int e = 0; e < 4; e++) accS[mt][nt][e] = 0.f;
        #pragma unroll
        for (int ks = 0; ks < 8; ks++) {
            const int kb = ks * 8 + 2 * c4;
            uint32_t afr[2][4];
            #pragma unroll
            for (int mt = 0; mt < 2; mt++) {
                int m = mrow0 + mt * 16;
                uint2 a01 = *(const uint2*)&Qs[(m + r4)     * AQW + kb];
                uint2 a23 = *(const uint2*)&Qs[(m + r4 + 8) * AQW + kb];
                afr[mt][0] = a01.x; afr[mt][1] = a23.x;
                afr[mt][2] = a01.y; afr[mt][3] = a23.y;
            }
            #pragma unroll
            for (int nt = 0; nt < 8; nt++) {
                uint2 bq = *(const uint2*)&Ks[(nt*8 + r4) * AQW + kb];
                uint32_t bfr[2] = { bq.x, bq.y };
                mma_tf32(accS[0][nt], afr[0], bfr);
                mma_tf32(accS[1][nt], afr[1], bfr);
            }
        }

        #pragma unroll
        for (int mt = 0; mt < 2; mt++) {
            float rmax_lo = -1e30f, rmax_hi = -1e30f;
            #pragma unroll
            for (int nt = 0; nt < 8; nt++) {
                rmax_lo = fmaxf(rmax_lo, fmaxf(accS[mt][nt][0], accS[mt][nt][1]));
                rmax_hi = fmaxf(rmax_hi, fmaxf(accS[mt][nt][2], accS[mt][nt][3]));
            }
            rmax_lo = fmaxf(rmax_lo, __shfl_xor_sync(0xffffffffu, rmax_lo, 1));
            rmax_lo = fmaxf(rmax_lo, __shfl_xor_sync(0xffffffffu, rmax_lo, 2));
            rmax_hi = fmaxf(rmax_hi, __shfl_xor_sync(0xffffffffu, rmax_hi, 1));
            rmax_hi = fmaxf(rmax_hi, __shfl_xor_sync(0xffffffffu, rmax_hi, 2));

            float mn_lo = fmaxf(m_lo[mt], rmax_lo);
            float mn_hi = fmaxf(m_hi[mt], rmax_hi);
            float corr_lo = __expf(m_lo[mt] - mn_lo);
            float corr_hi = __expf(m_hi[mt] - mn_hi);
            m_lo[mt] = mn_lo; m_hi[mt] = mn_hi;

            float rs_lo = 0.f, rs_hi = 0.f;
            #pragma unroll
            for (int nt = 0; nt < 8; nt++) {
                float p0 = __expf(accS[mt][nt][0] - mn_lo);
                float p1 = __expf(accS[mt][nt][1] - mn_lo);
                float p2 = __expf(accS[mt][nt][2] - mn_hi);
                float p3 = __expf(accS[mt][nt][3] - mn_hi);
                rs_lo += p0 + p1; rs_hi += p2 + p3;
                accS[mt][nt][0] = p0; accS[mt][nt][1] = p1;
                accS[mt][nt][2] = p2; accS[mt][nt][3] = p3;
            }
            rs_lo += __shfl_xor_sync(0xffffffffu, rs_lo, 1);
            rs_lo += __shfl_xor_sync(0xffffffffu, rs_lo, 2);
            rs_hi += __shfl_xor_sync(0xffffffffu, rs_hi, 1);
            rs_hi += __shfl_xor_sync(0xffffffffu, rs_hi, 2);
            l_lo[mt] = l_lo[mt] * corr_lo + rs_lo;
            l_hi[mt] = l_hi[mt] * corr_hi + rs_hi;

            #pragma unroll
            for (int nt = 0; nt < 8; nt++) {
                accO[mt][nt][0] *= corr_lo; accO[mt][nt][1] *= corr_lo;
                accO[mt][nt][2] *= corr_hi; accO[mt][nt][3] *= corr_hi;
            }
        }

        #pragma unroll
        for (int ks = 0; ks < 8; ks++) {
            uint32_t a_u[2][4];
            #pragma unroll
            for (int mt = 0; mt < 2; mt++) {
                float t0, t1, af;
                t0 = __shfl_sync(0xffffffffu, accS[mt][ks][0], srcA);
                t1 = __shfl_sync(0xffffffffu, accS[mt][ks][1], srcA);
                af = odd ? t1 : t0; a_u[mt][0] = to_tf32(af);
                t0 = __shfl_sync(0xffffffffu, accS[mt][ks][2], srcA);
                t1 = __shfl_sync(0xffffffffu, accS[mt][ks][3], srcA);
                af = odd ? t1 : t0; a_u[mt][1] = to_tf32(af);
                t0 = __shfl_sync(0xffffffffu, accS[mt][ks][0], srcB);
                t1 = __shfl_sync(0xffffffffu, accS[mt][ks][1], srcB);
                af = odd ? t1 : t0; a_u[mt][2] = to_tf32(af);
                t0 = __shfl_sync(0xffffffffu, accS[mt][ks][2], srcB);
                t1 = __shfl_sync(0xffffffffu, accS[mt][ks][3], srcB);
                af = odd ? t1 : t0; a_u[mt][3] = to_tf32(af);
            }
            const int kb = ks * 8 + 2 * c4;
            #pragma unroll
            for (int nt = 0; nt < 8; nt++) {
                uint2 bq = *(const uint2*)&Vt[(nt*8 + r4) * AQW + kb];
                uint32_t bfr[2] = { bq.x, bq.y };
                mma_tf32(accO[0][nt], a_u[0], bfr);
                mma_tf32(accO[1][nt], a_u[1], bfr);
            }
        }
    }

    #pragma unroll
    for (int mt = 0; mt < 2; mt++) {
        float il_lo = 1.0f / l_lo[mt], il_hi = 1.0f / l_hi[mt];
        int row_lo = q0 + mrow0 + mt * 16 + r4;
        float* o_lo = g_o + (size_t)(b * SEQ + row_lo) * Dm + h * HDIM;
        float* o_hi = o_lo + 8 * Dm;
        #pragma unroll
        for (int nt = 0; nt < 8; nt++) {
            float2 v;
            v.x = tf32r(accO[mt][nt][0] * il_lo); v.y = tf32r(accO[mt][nt][1] * il_lo);
            *(float2*)(o_lo + nt * 8 + 2 * c4) = v;
            v.x = tf32r(accO[mt][nt][2] * il_hi); v.y = tf32r(accO[mt][nt][3] * il_hi);
            *(float2*)(o_hi + nt * 8 + 2 * c4) = v;
        }
    }
}

// ---------------- launch ----------------
// Buffer ids: 0=g_h 1=g_qkv 2=g_o 3=g_x1 4=g_m 5=g_ma 6=g_wt ; -1 = external
extern "C" void kernel_launch(void* const* d_in, const int* in_sizes, int n_in,
                              void* d_out, int out_size) {
    const float* x      = (const float*)d_in[0];
    const float* ln1_g  = (const float*)d_in[1];
    const float* ln1_b  = (const float*)d_in[2];
    const float* lnm_g  = (const float*)d_in[3];
    const float* lnm_b  = (const float*)d_in[4];
    const float* qkv_w  = (const float*)d_in[5];
    const float* qkv_b  = (const float*)d_in[6];
    const float* proj_w = (const float*)d_in[7];
    const float* proj_b = (const float*)d_in[8];
    const float* fc1_w  = (const float*)d_in[9];
    const float* fc1_b  = (const float*)d_in[10];
    const float* fc2_w  = (const float*)d_in[11];
    const float* fc2_b  = (const float*)d_in[12];
    float* out = (float*)d_out;

    // idempotent, non-stream API calls (execute immediately, not captured)
    cudaFuncSetAttribute(attn_mma, cudaFuncAttributeMaxDynamicSharedMemorySize,
                         ATT_SMEM_BYTES);
    cudaFuncSetAttribute(gemm_mma<0>, cudaFuncAttributeMaxDynamicSharedMemorySize,
                         GEMM_SMEM_BYTES);
    cudaFuncSetAttribute(gemm_mma<1>, cudaFuncAttributeMaxDynamicSharedMemorySize,
                         GEMM_SMEM_BYTES);
    cudaFuncSetAttribute(gemm_mma<2>, cudaFuncAttributeMaxDynamicSharedMemorySize,
                         GEMM_SMEM_BYTES);

    // 1. LN1: g_h = LN(x)   (tf32-rounded)
    ln_kernel<<<ROWS, 256>>>(-1, x, ln1_g, ln1_b, 0);
    // 2. QKV: g_qkv = g_h @ qkv_w + qkv_b
    transpose_w<<<dim3(3 * Dm / 32, Dm / 32), dim3(32, 8)>>>(qkv_w, Dm, 3 * Dm);
    gemm_mma<0><<<dim3(3 * Dm / 128, ROWS / 128), 256, GEMM_SMEM_BYTES>>>(
        0, qkv_b, -1, nullptr, 1, nullptr, ROWS, 3 * Dm, Dm);
    // 3. attention (tensor-core flash, Q-tile 128)
    attn_mma<<<dim3(SEQ / 128, BATCH * HEADS), 128, ATT_SMEM_BYTES>>>();
    // 4. g_x1 = x + g_o @ proj_w + proj_b
    transpose_w<<<dim3(Dm / 32, Dm / 32), dim3(32, 8)>>>(proj_w, Dm, Dm);
    gemm_mma<1><<<dim3(Dm / 128, ROWS / 128), 256, GEMM_SMEM_BYTES>>>(
        2, proj_b, -1, x, 3, nullptr, ROWS, Dm, Dm);
    // 5. LNm: g_m = LN(g_x1)  (tf32-rounded)
    ln_kernel<<<ROWS, 256>>>(3, nullptr, lnm_g, lnm_b, 4);
    // 6. g_ma = gelu(g_m @ fc1_w + fc1_b)  (tf32-rounded)
    transpose_w<<<dim3(MLPD / 32, Dm / 32), dim3(32, 8)>>>(fc1_w, Dm, MLPD);
    gemm_mma<2><<<dim3(MLPD / 128, ROWS / 128), 256, GEMM_SMEM_BYTES>>>(
        4, fc1_b, -1, nullptr, 5, nullptr, ROWS, MLPD, Dm);
    // 7. out = g_x1 + g_ma @ fc2_w + fc2_b
    transpose_w<<<dim3(Dm / 32, MLPD / 32), dim3(32, 8)>>>(fc2_w, MLPD, Dm);
    gemm_mma<1><<<dim3(Dm / 128, ROWS / 128), 256, GEMM_SMEM_BYTES>>>(
        5, fc2_b, 3, nullptr, -1, out, ROWS, Dm, MLPD);
}